// round 1
// baseline (speedup 1.0000x reference)
#include <cuda_runtime.h>
#include <cuda_bf16.h>
#include <math.h>

// ---------------- problem constants ----------------
#define BB 2
#define LL 2048
#define DD 3584
#define HH 16
#define KVH 8
#define HDD 256
#define GROUPS (HH / KVH)
#define MM (BB * LL)          // 4096 rows for all GEMMs
#define WINDOW 1024
#define SOFT_CAP 50.0f

// ---------------- device scratch (no allocations allowed) ----------------
__device__ float g_Q[BB * LL * HH * HDD];     // 16.7M floats (64MB)  [B,L,H,HD]
__device__ float g_K[BB * LL * KVH * HDD];    // 8.4M  floats (32MB)  [B,L,KV,HD]
__device__ float g_V[BB * LL * KVH * HDD];    // 32MB                 [B,L,KV,HD]
__device__ float g_O[BB * LL * HH * HDD];     // 64MB                 [B,L,H,HD]
__device__ float g_cos[LL * (HDD / 2)];       // rope tables
__device__ float g_sin[LL * (HDD / 2)];

// =====================================================================
// SGEMM: C[M,N] = A[M,K] @ B[K,N], row-major, 128x128 tile, BK=8,
// 256 threads, 8x8 per-thread microtile. All dims multiples of 128/8.
// =====================================================================
__global__ void sgemm128(const float* __restrict__ A,
                         const float* __restrict__ B,
                         float* __restrict__ C,
                         int M, int N, int K)
{
    __shared__ float As[8][128];   // transposed: As[k][m]
    __shared__ float Bs[8][128];

    const int tid = threadIdx.x;
    const int row0 = blockIdx.y * 128;
    const int col0 = blockIdx.x * 128;
    const int ty = tid >> 4;         // 0..15 -> rows ty*8..+7
    const int tx = tid & 15;         // 0..15 -> cols tx*8..+7

    // global load assignments
    const int arow = tid >> 1;          // 0..127
    const int aseg = (tid & 1) * 4;     // 0 or 4
    const int brow = tid >> 5;          // 0..7
    const int bcol = (tid & 31) * 4;    // 0..124

    const float* Aptr = A + (size_t)(row0 + arow) * K + aseg;
    const float* Bptr = B + (size_t)brow * N + col0 + bcol;

    float acc[8][8];
#pragma unroll
    for (int i = 0; i < 8; i++)
#pragma unroll
        for (int j = 0; j < 8; j++) acc[i][j] = 0.f;

    for (int kb = 0; kb < K; kb += 8) {
        float4 av = *(const float4*)(Aptr + kb);
        float4 bv = *(const float4*)(Bptr + (size_t)kb * N);
        __syncthreads();   // previous iteration's smem reads complete
        As[aseg + 0][arow] = av.x;
        As[aseg + 1][arow] = av.y;
        As[aseg + 2][arow] = av.z;
        As[aseg + 3][arow] = av.w;
        *(float4*)&Bs[brow][bcol] = bv;
        __syncthreads();

#pragma unroll
        for (int k = 0; k < 8; k++) {
            float4 a0 = *(const float4*)&As[k][ty * 8];
            float4 a1 = *(const float4*)&As[k][ty * 8 + 4];
            float4 b0 = *(const float4*)&Bs[k][tx * 8];
            float4 b1 = *(const float4*)&Bs[k][tx * 8 + 4];
            float a[8] = {a0.x, a0.y, a0.z, a0.w, a1.x, a1.y, a1.z, a1.w};
            float b[8] = {b0.x, b0.y, b0.z, b0.w, b1.x, b1.y, b1.z, b1.w};
#pragma unroll
            for (int i = 0; i < 8; i++)
#pragma unroll
                for (int j = 0; j < 8; j++)
                    acc[i][j] += a[i] * b[j];
        }
    }

#pragma unroll
    for (int i = 0; i < 8; i++) {
        int row = row0 + ty * 8 + i;
        float4 c0 = make_float4(acc[i][0], acc[i][1], acc[i][2], acc[i][3]);
        float4 c1 = make_float4(acc[i][4], acc[i][5], acc[i][6], acc[i][7]);
        *(float4*)&C[(size_t)row * N + col0 + tx * 8]     = c0;
        *(float4*)&C[(size_t)row * N + col0 + tx * 8 + 4] = c1;
    }
}

// =====================================================================
// RoPE table: cos/sin for pos in [0,L), i in [0,128). Double precision
// angle to stay well inside the 1e-3 tolerance vs the fp32 reference.
// =====================================================================
__global__ void rope_table_kernel()
{
    int idx = blockIdx.x * blockDim.x + threadIdx.x;
    if (idx >= LL * (HDD / 2)) return;
    int p = idx / (HDD / 2);
    int i = idx % (HDD / 2);
    double invf = pow(10000.0, -((double)(2 * i)) / (double)HDD);
    double f = (double)p * invf;
    double s, c;
    sincos(f, &s, &c);
    g_cos[idx] = (float)c;
    g_sin[idx] = (float)s;
}

// RoPE apply, in place on [B,L,NH,HD] buffer (rotate-half style)
__global__ void rope_apply_kernel(float* __restrict__ buf,
                                  const int* __restrict__ pos_ids, int NH)
{
    int idx = blockIdx.x * blockDim.x + threadIdx.x;
    int total = BB * LL * NH * (HDD / 2);
    if (idx >= total) return;
    int i = idx & 127;                  // 0..127
    int n = (idx >> 7) % NH;
    int l = (idx >> 7) / NH % LL;
    int b = idx / (128 * NH * LL);
    int p = pos_ids[b * LL + l];
    if (p < 0) p = 0;
    if (p >= LL) p = LL - 1;
    float c = g_cos[p * (HDD / 2) + i];
    float s = g_sin[p * (HDD / 2) + i];
    size_t base = (((size_t)b * LL + l) * NH + n) * HDD;
    float x1 = buf[base + i];
    float x2 = buf[base + i + 128];
    buf[base + i]       = x1 * c - x2 * s;
    buf[base + i + 128] = x1 * s + x2 * c;
}

// =====================================================================
// Flash attention, fp32, softcap + causal + sliding window, no 1/sqrt(d).
// One block = (b, h, 64-query tile). 256 threads.
// Smem: Qs[64][260] Vs[64][260] KsT[64][65] Ssm[64][65] + m/l/alpha.
// =====================================================================
#define FL_SMEM_FLOATS (64*260 + 64*260 + 64*65 + 64*65 + 3*64)
#define FL_SMEM_BYTES  (FL_SMEM_FLOATS * 4)

__global__ void flash_kernel(const float* __restrict__ Q,
                             const float* __restrict__ K,
                             const float* __restrict__ V,
                             float* __restrict__ O)
{
    extern __shared__ float sm[];
    float* Qs  = sm;                    // [64][260]
    float* Vs  = Qs + 64 * 260;         // [64][260]
    float* KsT = Vs + 64 * 260;         // [64 hd][65 kv]
    float* Ssm = KsT + 64 * 65;         // [64][65]
    float* mrow = Ssm + 64 * 65;        // [64]
    float* lrow = mrow + 64;            // [64]
    float* arow = lrow + 64;            // [64]

    const int tid = threadIdx.x;
    const int bid = blockIdx.x;
    const int qt = bid & 31;            // 32 q-tiles
    const int h  = (bid >> 5) & (HH - 1);
    const int b  = bid >> 9;            // / (32*16)
    const int q0 = qt << 6;
    const int hk = h / GROUPS;

    const int ty = tid >> 4;            // 0..15
    const int tx = tid & 15;            // 0..15
    const int r0 = ty << 2;             // PV / S rows: 4*ty..+3
    const int c0 = tx << 4;             // PV cols: 16*tx..+15

    // load Q tile [64 rows][256] (coalesced float4)
    for (int idx = tid; idx < 64 * 64; idx += 256) {
        int r = idx >> 6, f4 = idx & 63;
        float4 v = *(const float4*)&Q[((((size_t)b * LL) + q0 + r) * HH + h) * HDD + 4 * f4];
        *(float4*)&Qs[r * 260 + 4 * f4] = v;
    }
    if (tid < 64) { mrow[tid] = -1e30f; lrow[tid] = 0.f; }

    float oacc[4][16];
#pragma unroll
    for (int i = 0; i < 4; i++)
#pragma unroll
        for (int c = 0; c < 16; c++) oacc[i][c] = 0.f;

    int lo = q0 - (WINDOW - 1);
    if (lo < 0) lo = 0;
    const int kt0 = lo >> 6;
    const int kt1 = q0 >> 6;

    for (int kt = kt0; kt <= kt1; kt++) {
        const int k0 = kt << 6;
        __syncthreads();   // previous tile's smem readers done (also covers Q/init on first iter)

        // load V tile [64][256]
        for (int idx = tid; idx < 64 * 64; idx += 256) {
            int r = idx >> 6, f4 = idx & 63;
            float4 v = *(const float4*)&V[((((size_t)b * LL) + k0 + r) * KVH + hk) * HDD + 4 * f4];
            *(float4*)&Vs[r * 260 + 4 * f4] = v;
        }

        // S = Q @ K^T in four 64-wide hd chunks
        float acc[4][4];
#pragma unroll
        for (int i = 0; i < 4; i++)
#pragma unroll
            for (int j = 0; j < 4; j++) acc[i][j] = 0.f;

        for (int cc = 0; cc < 4; cc++) {
            if (cc) __syncthreads();     // previous chunk reads done
            // load & transpose K chunk: KsT[hd][kv]
            for (int idx = tid; idx < 64 * 16; idx += 256) {
                int r = idx >> 4, f4 = idx & 15;
                float4 kv4 = *(const float4*)&K[((((size_t)b * LL) + k0 + r) * KVH + hk) * HDD + cc * 64 + 4 * f4];
                KsT[(4 * f4 + 0) * 65 + r] = kv4.x;
                KsT[(4 * f4 + 1) * 65 + r] = kv4.y;
                KsT[(4 * f4 + 2) * 65 + r] = kv4.z;
                KsT[(4 * f4 + 3) * 65 + r] = kv4.w;
            }
            __syncthreads();
            const int off = cc * 64;
#pragma unroll 4
            for (int k = 0; k < 64; k++) {
                float a0 = Qs[(r0 + 0) * 260 + off + k];
                float a1 = Qs[(r0 + 1) * 260 + off + k];
                float a2 = Qs[(r0 + 2) * 260 + off + k];
                float a3 = Qs[(r0 + 3) * 260 + off + k];
                float b0 = KsT[k * 65 + 4 * tx + 0];
                float b1 = KsT[k * 65 + 4 * tx + 1];
                float b2 = KsT[k * 65 + 4 * tx + 2];
                float b3 = KsT[k * 65 + 4 * tx + 3];
                acc[0][0] += a0 * b0; acc[0][1] += a0 * b1; acc[0][2] += a0 * b2; acc[0][3] += a0 * b3;
                acc[1][0] += a1 * b0; acc[1][1] += a1 * b1; acc[1][2] += a1 * b2; acc[1][3] += a1 * b3;
                acc[2][0] += a2 * b0; acc[2][1] += a2 * b1; acc[2][2] += a2 * b2; acc[2][3] += a2 * b3;
                acc[3][0] += a3 * b0; acc[3][1] += a3 * b1; acc[3][2] += a3 * b2; acc[3][3] += a3 * b3;
            }
        }

        // softcap (before mask!) + mask -> Ssm
#pragma unroll
        for (int i = 0; i < 4; i++) {
            int q = q0 + r0 + i;
#pragma unroll
            for (int j = 0; j < 4; j++) {
                int kv = k0 + 4 * tx + j;
                float s = SOFT_CAP * tanhf(acc[i][j] * (1.0f / SOFT_CAP));
                bool ok = (kv <= q) && (kv > q - WINDOW);
                Ssm[(r0 + i) * 65 + 4 * tx + j] = ok ? s : -1e30f;
            }
        }
        __syncthreads();

        // online softmax row stats (one thread per row)
        if (tid < 64) {
            int r = tid;
            float tm = -1e30f;
            for (int c = 0; c < 64; c++) tm = fmaxf(tm, Ssm[r * 65 + c]);
            float mold = mrow[r];
            float mnew = fmaxf(mold, tm);
            float alpha;
            if (mnew <= -0.9e30f) {
                alpha = 1.0f;                      // everything masked so far
                for (int c = 0; c < 64; c++) Ssm[r * 65 + c] = 0.f;
            } else {
                alpha = __expf(mold - mnew);       // mold=-1e30 -> 0
                float lsum = 0.f;
                for (int c = 0; c < 64; c++) {
                    float p = __expf(Ssm[r * 65 + c] - mnew);
                    Ssm[r * 65 + c] = p;
                    lsum += p;
                }
                lrow[r] = lrow[r] * alpha + lsum;
            }
            mrow[r] = mnew;
            arow[r] = alpha;
        }
        __syncthreads();

        // O = O*alpha + P @ V
        float al[4];
#pragma unroll
        for (int i = 0; i < 4; i++) al[i] = arow[r0 + i];
#pragma unroll
        for (int i = 0; i < 4; i++)
#pragma unroll
            for (int c = 0; c < 16; c++) oacc[i][c] *= al[i];

#pragma unroll 2
        for (int k = 0; k < 64; k++) {
            float p0 = Ssm[(r0 + 0) * 65 + k];
            float p1 = Ssm[(r0 + 1) * 65 + k];
            float p2 = Ssm[(r0 + 2) * 65 + k];
            float p3 = Ssm[(r0 + 3) * 65 + k];
            const float4* vr = (const float4*)&Vs[k * 260 + c0];
#pragma unroll
            for (int m = 0; m < 4; m++) {
                float4 v = vr[m];
                oacc[0][4*m+0] += p0 * v.x; oacc[0][4*m+1] += p0 * v.y;
                oacc[0][4*m+2] += p0 * v.z; oacc[0][4*m+3] += p0 * v.w;
                oacc[1][4*m+0] += p1 * v.x; oacc[1][4*m+1] += p1 * v.y;
                oacc[1][4*m+2] += p1 * v.z; oacc[1][4*m+3] += p1 * v.w;
                oacc[2][4*m+0] += p2 * v.x; oacc[2][4*m+1] += p2 * v.y;
                oacc[2][4*m+2] += p2 * v.z; oacc[2][4*m+3] += p2 * v.w;
                oacc[3][4*m+0] += p3 * v.x; oacc[3][4*m+1] += p3 * v.y;
                oacc[3][4*m+2] += p3 * v.z; oacc[3][4*m+3] += p3 * v.w;
            }
        }
    }

    // epilogue: normalize by l, write [B,L,H,HD]
#pragma unroll
    for (int i = 0; i < 4; i++) {
        float linv = 1.0f / lrow[r0 + i];
        size_t base = ((((size_t)b * LL) + q0 + r0 + i) * HH + h) * HDD + c0;
#pragma unroll
        for (int m = 0; m < 4; m++) {
            float4 v = make_float4(oacc[i][4*m+0] * linv, oacc[i][4*m+1] * linv,
                                   oacc[i][4*m+2] * linv, oacc[i][4*m+3] * linv);
            *(float4*)&O[base + 4 * m] = v;
        }
    }
}

// =====================================================================
// host launcher
// =====================================================================
extern "C" void kernel_launch(void* const* d_in, const int* in_sizes, int n_in,
                              void* d_out, int out_size)
{
    (void)in_sizes; (void)n_in; (void)out_size;
    const float* X   = (const float*)d_in[0];
    const int*   pos = (const int*)d_in[1];
    const float* Wq  = (const float*)d_in[2];
    const float* Wk  = (const float*)d_in[3];
    const float* Wv  = (const float*)d_in[4];
    const float* Wo  = (const float*)d_in[5];
    float* out = (float*)d_out;

    float *Qb, *Kb, *Vb, *Ob;
    cudaGetSymbolAddress((void**)&Qb, g_Q);
    cudaGetSymbolAddress((void**)&Kb, g_K);
    cudaGetSymbolAddress((void**)&Vb, g_V);
    cudaGetSymbolAddress((void**)&Ob, g_O);

    cudaFuncSetAttribute(flash_kernel, cudaFuncAttributeMaxDynamicSharedMemorySize,
                         FL_SMEM_BYTES);

    // QKV projections
    sgemm128<<<dim3((HH * HDD) / 128, MM / 128), 256>>>(X, Wq, Qb, MM, HH * HDD, DD);
    sgemm128<<<dim3((KVH * HDD) / 128, MM / 128), 256>>>(X, Wk, Kb, MM, KVH * HDD, DD);
    sgemm128<<<dim3((KVH * HDD) / 128, MM / 128), 256>>>(X, Wv, Vb, MM, KVH * HDD, DD);

    // RoPE
    {
        int n = LL * (HDD / 2);
        rope_table_kernel<<<(n + 255) / 256, 256>>>();
        int nq = BB * LL * HH * (HDD / 2);
        rope_apply_kernel<<<(nq + 255) / 256, 256>>>(Qb, pos, HH);
        int nk = BB * LL * KVH * (HDD / 2);
        rope_apply_kernel<<<(nk + 255) / 256, 256>>>(Kb, pos, KVH);
    }

    // attention
    flash_kernel<<<BB * HH * (LL / 64), 256, FL_SMEM_BYTES>>>(Qb, Kb, Vb, Ob);

    // output projection
    sgemm128<<<dim3(DD / 128, MM / 128), 256>>>(Ob, Wo, out, MM, DD, HH * HDD);
}

// round 5
// speedup vs baseline: 1.2792x; 1.2792x over previous
#include <cuda_runtime.h>
#include <cuda_bf16.h>
#include <math.h>
#include <stdint.h>

// ---------------- problem constants ----------------
#define BB 2
#define LL 2048
#define DD 3584
#define HH 16
#define KVH 8
#define HDD 256
#define GROUPS (HH / KVH)
#define MM (BB * LL)          // 4096 rows for all GEMMs
#define WINDOW 1024
#define SOFT_CAP 50.0f

// ---------------- device scratch (no runtime allocations allowed) ----------------
__device__ float g_Q[BB * LL * HH * HDD];       // [B,L,H,HD]
__device__ float g_K[BB * LL * KVH * HDD];      // [B,L,KV,HD]
__device__ float g_V[BB * LL * KVH * HDD];      // [B,L,KV,HD]
__device__ float g_O[BB * LL * HH * HDD];       // [B,L,H,HD]
__device__ float g_cos[LL * (HDD / 2)];
__device__ float g_sin[LL * (HDD / 2)];
// transposed weights [N,K]
__device__ float g_WqT[(HH * HDD) * DD];
__device__ float g_WkT[(KVH * HDD) * DD];
__device__ float g_WvT[(KVH * HDD) * DD];
__device__ float g_WoT[DD * (HH * HDD)];

// =====================================================================
// helpers
// =====================================================================
__device__ __forceinline__ uint32_t smem_u32(const void* p)
{
    uint32_t a;
    asm("{ .reg .u64 t; cvta.to.shared.u64 t, %1; cvt.u32.u64 %0, t; }" : "=r"(a) : "l"(p));
    return a;
}

__device__ __forceinline__ void ldsm4(uint32_t* r, uint32_t addr)
{
    asm volatile("ldmatrix.sync.aligned.m8n8.x4.shared.b16 {%0,%1,%2,%3}, [%4];"
                 : "=r"(r[0]), "=r"(r[1]), "=r"(r[2]), "=r"(r[3]) : "r"(addr));
}

__device__ __forceinline__ void mma_tf32(float* c, const uint32_t* a,
                                         uint32_t b0, uint32_t b1)
{
    asm volatile(
        "mma.sync.aligned.m16n8k8.row.col.f32.tf32.tf32.f32 "
        "{%0,%1,%2,%3}, {%4,%5,%6,%7}, {%8,%9}, {%0,%1,%2,%3};"
        : "+f"(c[0]), "+f"(c[1]), "+f"(c[2]), "+f"(c[3])
        : "r"(a[0]), "r"(a[1]), "r"(a[2]), "r"(a[3]), "r"(b0), "r"(b1));
}

// split fp32 into two tf32-representable parts (both masked to valid tf32)
__device__ __forceinline__ void split2(float x, float& h, float& l)
{
    uint32_t hb = __float_as_uint(x) & 0xFFFFE000u;
    float hf = __uint_as_float(hb);
    float lf = x - hf;                       // exact
    h = hf;
    l = __uint_as_float(__float_as_uint(lf) & 0xFFFFE000u);
}

// =====================================================================
// transpose: out[C,R] = in[R,C]^T   (R,C multiples of 32)
// =====================================================================
__global__ void transpose_kernel(const float* __restrict__ in, float* __restrict__ out,
                                 int R, int C)
{
    __shared__ float t[32][33];
    int c0 = blockIdx.x * 32, r0 = blockIdx.y * 32;
    int tx = threadIdx.x, ty = threadIdx.y;   // (32, 8)
#pragma unroll
    for (int i = 0; i < 32; i += 8)
        t[ty + i][tx] = in[(size_t)(r0 + ty + i) * C + c0 + tx];
    __syncthreads();
#pragma unroll
    for (int i = 0; i < 32; i += 8)
        out[(size_t)(c0 + ty + i) * R + r0 + tx] = t[tx][ty + i];
}

// =====================================================================
// mma.sync tf32x2 GEMM: C[M,N] = A[M,K] @ BT[N,K]^T
// 128x128 CTA tile, 8 warps (2x4) of 64x32, BK=16, double-buffered smem.
// Smem row stride 80B (16 floats + 16B pad) -> conflict-free ldmatrix.
// =====================================================================
#define BM 128
#define BN 128
#define BKF 16
#define ROWB 80                         // bytes per smem row
#define ARR_B (BM * ROWB)               // 10240 bytes per array
#define STAGE_B (4 * ARR_B)             // Ah, Al, Bh, Bl = 40960
#define GSMEM_BYTES (2 * STAGE_B)       // 81920

__global__ __launch_bounds__(256, 1)
void gemm_mma_tf32(const float* __restrict__ A, const float* __restrict__ BT,
                   float* __restrict__ C, int M, int N, int K)
{
    extern __shared__ float sm[];
    const uint32_t smem_base = smem_u32(sm);

    const int tid = threadIdx.x;
    const int wid = tid >> 5;
    const int lane = tid & 31;
    const int wm = wid & 1;              // 0..1 : 64-row slab
    const int wn = wid >> 1;             // 0..3 : 32-col slab
    const int row0 = blockIdx.y * BM;
    const int col0 = blockIdx.x * BN;

    // ldmatrix per-lane byte offsets (within Ah / Bh arrays)
    const uint32_t aoff = (uint32_t)((wm * 64 + (lane & 15)) * ROWB + ((lane & 16) ? 16 : 0));
    const uint32_t boff = (uint32_t)((wn * 32 + (lane & 7) + ((lane & 16) ? 8 : 0)) * ROWB
                                     + ((lane & 8) ? 16 : 0));

    // staging assignments: 512 float4 slots per matrix per chunk, 2 per thread
    const int r0s = (tid + 0) >> 2, s0s = (tid + 0) & 3;
    const int r1s = (tid + 256) >> 2, s1s = (tid + 256) & 3;

    float cacc[4][4][4];
#pragma unroll
    for (int mt = 0; mt < 4; mt++)
#pragma unroll
        for (int nt = 0; nt < 4; nt++)
#pragma unroll
            for (int i = 0; i < 4; i++) cacc[mt][nt][i] = 0.f;

    const int NC = K / BKF;
    float4 aR[2], bR[2];

    // prologue load
    {
        aR[0] = *(const float4*)(A + (size_t)(row0 + r0s) * K + 0 + s0s * 4);
        aR[1] = *(const float4*)(A + (size_t)(row0 + r1s) * K + 0 + s1s * 4);
        bR[0] = *(const float4*)(BT + (size_t)(col0 + r0s) * K + 0 + s0s * 4);
        bR[1] = *(const float4*)(BT + (size_t)(col0 + r1s) * K + 0 + s1s * 4);
    }

    for (int ch = 0; ch < NC; ch++) {
        const int s = ch & 1;
        float* Ah = sm + s * (STAGE_B / 4);
        float* Al = Ah + ARR_B / 4;
        float* Bh = Al + ARR_B / 4;
        float* Bl = Bh + ARR_B / 4;

        // store staged chunk (split hi/lo)
#pragma unroll
        for (int i = 0; i < 2; i++) {
            int r = i ? r1s : r0s, sg = i ? s1s : s0s;
            float4 v = aR[i], h, l;
            split2(v.x, h.x, l.x); split2(v.y, h.y, l.y);
            split2(v.z, h.z, l.z); split2(v.w, h.w, l.w);
            *(float4*)&Ah[r * (ROWB / 4) + sg * 4] = h;
            *(float4*)&Al[r * (ROWB / 4) + sg * 4] = l;
            v = bR[i];
            split2(v.x, h.x, l.x); split2(v.y, h.y, l.y);
            split2(v.z, h.z, l.z); split2(v.w, h.w, l.w);
            *(float4*)&Bh[r * (ROWB / 4) + sg * 4] = h;
            *(float4*)&Bl[r * (ROWB / 4) + sg * 4] = l;
        }
        __syncthreads();

        // prefetch next chunk
        if (ch + 1 < NC) {
            int kb = (ch + 1) * BKF;
            aR[0] = *(const float4*)(A + (size_t)(row0 + r0s) * K + kb + s0s * 4);
            aR[1] = *(const float4*)(A + (size_t)(row0 + r1s) * K + kb + s1s * 4);
            bR[0] = *(const float4*)(BT + (size_t)(col0 + r0s) * K + kb + s0s * 4);
            bR[1] = *(const float4*)(BT + (size_t)(col0 + r1s) * K + kb + s1s * 4);
        }

        // compute 2 k8 steps from stage s
        const uint32_t sb = smem_base + s * STAGE_B;
#pragma unroll
        for (int k8 = 0; k8 < 2; k8++) {
            uint32_t ab = sb + aoff + k8 * 32;
            uint32_t bb = sb + 2 * ARR_B + boff + k8 * 32;
            uint32_t ah[4][4], al[4][4], bh[2][4], bl[2][4];
#pragma unroll
            for (int mt = 0; mt < 4; mt++) {
                ldsm4(ah[mt], ab + mt * (16 * ROWB));
                ldsm4(al[mt], ab + ARR_B + mt * (16 * ROWB));
            }
#pragma unroll
            for (int np = 0; np < 2; np++) {
                ldsm4(bh[np], bb + np * (16 * ROWB));
                ldsm4(bl[np], bb + ARR_B + np * (16 * ROWB));
            }
#pragma unroll
            for (int mt = 0; mt < 4; mt++) {
#pragma unroll
                for (int nt = 0; nt < 4; nt++) {
                    const int np = nt >> 1, o = (nt & 1) * 2;
                    mma_tf32(cacc[mt][nt], ah[mt], bh[np][o], bh[np][o + 1]);
                    mma_tf32(cacc[mt][nt], ah[mt], bl[np][o], bl[np][o + 1]);
                    mma_tf32(cacc[mt][nt], al[mt], bh[np][o], bh[np][o + 1]);
                }
            }
        }
        // no second barrier needed: next iteration's stores hit the other
        // stage, and the barrier after those stores protects this stage.
    }

    // epilogue
#pragma unroll
    for (int mt = 0; mt < 4; mt++) {
        int r = row0 + wm * 64 + mt * 16 + (lane >> 2);
#pragma unroll
        for (int nt = 0; nt < 4; nt++) {
            int c = col0 + wn * 32 + nt * 8 + 2 * (lane & 3);
            float2 v0 = make_float2(cacc[mt][nt][0], cacc[mt][nt][1]);
            float2 v1 = make_float2(cacc[mt][nt][2], cacc[mt][nt][3]);
            *(float2*)&C[(size_t)r * N + c]       = v0;
            *(float2*)&C[(size_t)(r + 8) * N + c] = v1;
        }
    }
}

// =====================================================================
// RoPE (unchanged, passing)
// =====================================================================
__global__ void rope_table_kernel()
{
    int idx = blockIdx.x * blockDim.x + threadIdx.x;
    if (idx >= LL * (HDD / 2)) return;
    int p = idx / (HDD / 2);
    int i = idx % (HDD / 2);
    double invf = pow(10000.0, -((double)(2 * i)) / (double)HDD);
    double f = (double)p * invf;
    double s, c;
    sincos(f, &s, &c);
    g_cos[idx] = (float)c;
    g_sin[idx] = (float)s;
}

__global__ void rope_apply_kernel(float* __restrict__ buf,
                                  const int* __restrict__ pos_ids, int NH)
{
    int idx = blockIdx.x * blockDim.x + threadIdx.x;
    int total = BB * LL * NH * (HDD / 2);
    if (idx >= total) return;
    int i = idx & 127;
    int n = (idx >> 7) % NH;
    int l = (idx >> 7) / NH % LL;
    int b = idx / (128 * NH * LL);
    int p = pos_ids[b * LL + l];
    if (p < 0) p = 0;
    if (p >= LL) p = LL - 1;
    float c = g_cos[p * (HDD / 2) + i];
    float s = g_sin[p * (HDD / 2) + i];
    size_t base = (((size_t)b * LL + l) * NH + n) * HDD;
    float x1 = buf[base + i];
    float x2 = buf[base + i + 128];
    buf[base + i]       = x1 * c - x2 * s;
    buf[base + i + 128] = x1 * s + x2 * c;
}

// =====================================================================
// Flash attention (unchanged, passing)
// =====================================================================
#define FL_SMEM_FLOATS (64*260 + 64*260 + 64*65 + 64*65 + 3*64)
#define FL_SMEM_BYTES  (FL_SMEM_FLOATS * 4)

__global__ void flash_kernel(const float* __restrict__ Q,
                             const float* __restrict__ K,
                             const float* __restrict__ V,
                             float* __restrict__ O)
{
    extern __shared__ float sm[];
    float* Qs  = sm;
    float* Vs  = Qs + 64 * 260;
    float* KsT = Vs + 64 * 260;
    float* Ssm = KsT + 64 * 65;
    float* mrow = Ssm + 64 * 65;
    float* lrow = mrow + 64;
    float* arow = lrow + 64;

    const int tid = threadIdx.x;
    const int bid = blockIdx.x;
    const int qt = bid & 31;
    const int h  = (bid >> 5) & (HH - 1);
    const int b  = bid >> 9;
    const int q0 = qt << 6;
    const int hk = h / GROUPS;

    const int ty = tid >> 4;
    const int tx = tid & 15;
    const int r0 = ty << 2;
    const int c0 = tx << 4;

    for (int idx = tid; idx < 64 * 64; idx += 256) {
        int r = idx >> 6, f4 = idx & 63;
        float4 v = *(const float4*)&Q[((((size_t)b * LL) + q0 + r) * HH + h) * HDD + 4 * f4];
        *(float4*)&Qs[r * 260 + 4 * f4] = v;
    }
    if (tid < 64) { mrow[tid] = -1e30f; lrow[tid] = 0.f; }

    float oacc[4][16];
#pragma unroll
    for (int i = 0; i < 4; i++)
#pragma unroll
        for (int c = 0; c < 16; c++) oacc[i][c] = 0.f;

    int lo = q0 - (WINDOW - 1);
    if (lo < 0) lo = 0;
    const int kt0 = lo >> 6;
    const int kt1 = q0 >> 6;

    for (int kt = kt0; kt <= kt1; kt++) {
        const int k0 = kt << 6;
        __syncthreads();

        for (int idx = tid; idx < 64 * 64; idx += 256) {
            int r = idx >> 6, f4 = idx & 63;
            float4 v = *(const float4*)&V[((((size_t)b * LL) + k0 + r) * KVH + hk) * HDD + 4 * f4];
            *(float4*)&Vs[r * 260 + 4 * f4] = v;
        }

        float acc[4][4];
#pragma unroll
        for (int i = 0; i < 4; i++)
#pragma unroll
            for (int j = 0; j < 4; j++) acc[i][j] = 0.f;

        for (int cc = 0; cc < 4; cc++) {
            if (cc) __syncthreads();
            for (int idx = tid; idx < 64 * 16; idx += 256) {
                int r = idx >> 4, f4 = idx & 15;
                float4 kv4 = *(const float4*)&K[((((size_t)b * LL) + k0 + r) * KVH + hk) * HDD + cc * 64 + 4 * f4];
                KsT[(4 * f4 + 0) * 65 + r] = kv4.x;
                KsT[(4 * f4 + 1) * 65 + r] = kv4.y;
                KsT[(4 * f4 + 2) * 65 + r] = kv4.z;
                KsT[(4 * f4 + 3) * 65 + r] = kv4.w;
            }
            __syncthreads();
            const int off = cc * 64;
#pragma unroll 4
            for (int k = 0; k < 64; k++) {
                float a0 = Qs[(r0 + 0) * 260 + off + k];
                float a1 = Qs[(r0 + 1) * 260 + off + k];
                float a2 = Qs[(r0 + 2) * 260 + off + k];
                float a3 = Qs[(r0 + 3) * 260 + off + k];
                float b0 = KsT[k * 65 + 4 * tx + 0];
                float b1 = KsT[k * 65 + 4 * tx + 1];
                float b2 = KsT[k * 65 + 4 * tx + 2];
                float b3 = KsT[k * 65 + 4 * tx + 3];
                acc[0][0] += a0 * b0; acc[0][1] += a0 * b1; acc[0][2] += a0 * b2; acc[0][3] += a0 * b3;
                acc[1][0] += a1 * b0; acc[1][1] += a1 * b1; acc[1][2] += a1 * b2; acc[1][3] += a1 * b3;
                acc[2][0] += a2 * b0; acc[2][1] += a2 * b1; acc[2][2] += a2 * b2; acc[2][3] += a2 * b3;
                acc[3][0] += a3 * b0; acc[3][1] += a3 * b1; acc[3][2] += a3 * b2; acc[3][3] += a3 * b3;
            }
        }

#pragma unroll
        for (int i = 0; i < 4; i++) {
            int q = q0 + r0 + i;
#pragma unroll
            for (int j = 0; j < 4; j++) {
                int kv = k0 + 4 * tx + j;
                float s = SOFT_CAP * tanhf(acc[i][j] * (1.0f / SOFT_CAP));
                bool ok = (kv <= q) && (kv > q - WINDOW);
                Ssm[(r0 + i) * 65 + 4 * tx + j] = ok ? s : -1e30f;
            }
        }
        __syncthreads();

        if (tid < 64) {
            int r = tid;
            float tm = -1e30f;
            for (int c = 0; c < 64; c++) tm = fmaxf(tm, Ssm[r * 65 + c]);
            float mold = mrow[r];
            float mnew = fmaxf(mold, tm);
            float alpha;
            if (mnew <= -0.9e30f) {
                alpha = 1.0f;
                for (int c = 0; c < 64; c++) Ssm[r * 65 + c] = 0.f;
            } else {
                alpha = __expf(mold - mnew);
                float lsum = 0.f;
                for (int c = 0; c < 64; c++) {
                    float p = __expf(Ssm[r * 65 + c] - mnew);
                    Ssm[r * 65 + c] = p;
                    lsum += p;
                }
                lrow[r] = lrow[r] * alpha + lsum;
            }
            mrow[r] = mnew;
            arow[r] = alpha;
        }
        __syncthreads();

        float al[4];
#pragma unroll
        for (int i = 0; i < 4; i++) al[i] = arow[r0 + i];
#pragma unroll
        for (int i = 0; i < 4; i++)
#pragma unroll
            for (int c = 0; c < 16; c++) oacc[i][c] *= al[i];

#pragma unroll 2
        for (int k = 0; k < 64; k++) {
            float p0 = Ssm[(r0 + 0) * 65 + k];
            float p1 = Ssm[(r0 + 1) * 65 + k];
            float p2 = Ssm[(r0 + 2) * 65 + k];
            float p3 = Ssm[(r0 + 3) * 65 + k];
            const float4* vr = (const float4*)&Vs[k * 260 + c0];
#pragma unroll
            for (int m = 0; m < 4; m++) {
                float4 v = vr[m];
                oacc[0][4*m+0] += p0 * v.x; oacc[0][4*m+1] += p0 * v.y;
                oacc[0][4*m+2] += p0 * v.z; oacc[0][4*m+3] += p0 * v.w;
                oacc[1][4*m+0] += p1 * v.x; oacc[1][4*m+1] += p1 * v.y;
                oacc[1][4*m+2] += p1 * v.z; oacc[1][4*m+3] += p1 * v.w;
                oacc[2][4*m+0] += p2 * v.x; oacc[2][4*m+1] += p2 * v.y;
                oacc[2][4*m+2] += p2 * v.z; oacc[2][4*m+3] += p2 * v.w;
                oacc[3][4*m+0] += p3 * v.x; oacc[3][4*m+1] += p3 * v.y;
                oacc[3][4*m+2] += p3 * v.z; oacc[3][4*m+3] += p3 * v.w;
            }
        }
    }

#pragma unroll
    for (int i = 0; i < 4; i++) {
        float linv = 1.0f / lrow[r0 + i];
        size_t base = ((((size_t)b * LL) + q0 + r0 + i) * HH + h) * HDD + c0;
#pragma unroll
        for (int m = 0; m < 4; m++) {
            float4 v = make_float4(oacc[i][4*m+0] * linv, oacc[i][4*m+1] * linv,
                                   oacc[i][4*m+2] * linv, oacc[i][4*m+3] * linv);
            *(float4*)&O[base + 4 * m] = v;
        }
    }
}

// =====================================================================
// host launcher
// =====================================================================
extern "C" void kernel_launch(void* const* d_in, const int* in_sizes, int n_in,
                              void* d_out, int out_size)
{
    (void)in_sizes; (void)n_in; (void)out_size;
    const float* X   = (const float*)d_in[0];
    const int*   pos = (const int*)d_in[1];
    const float* Wq  = (const float*)d_in[2];
    const float* Wk  = (const float*)d_in[3];
    const float* Wv  = (const float*)d_in[4];
    const float* Wo  = (const float*)d_in[5];
    float* out = (float*)d_out;

    float *Qb, *Kb, *Vb, *Ob, *WqT, *WkT, *WvT, *WoT;
    cudaGetSymbolAddress((void**)&Qb, g_Q);
    cudaGetSymbolAddress((void**)&Kb, g_K);
    cudaGetSymbolAddress((void**)&Vb, g_V);
    cudaGetSymbolAddress((void**)&Ob, g_O);
    cudaGetSymbolAddress((void**)&WqT, g_WqT);
    cudaGetSymbolAddress((void**)&WkT, g_WkT);
    cudaGetSymbolAddress((void**)&WvT, g_WvT);
    cudaGetSymbolAddress((void**)&WoT, g_WoT);

    cudaFuncSetAttribute(flash_kernel, cudaFuncAttributeMaxDynamicSharedMemorySize,
                         FL_SMEM_BYTES);
    cudaFuncSetAttribute(gemm_mma_tf32, cudaFuncAttributeMaxDynamicSharedMemorySize,
                         GSMEM_BYTES);

    // transpose weights -> [N, K]
    {
        dim3 blk(32, 8);
        transpose_kernel<<<dim3((HH * HDD) / 32, DD / 32), blk>>>(Wq, WqT, DD, HH * HDD);
        transpose_kernel<<<dim3((KVH * HDD) / 32, DD / 32), blk>>>(Wk, WkT, DD, KVH * HDD);
        transpose_kernel<<<dim3((KVH * HDD) / 32, DD / 32), blk>>>(Wv, WvT, DD, KVH * HDD);
        transpose_kernel<<<dim3(DD / 32, (HH * HDD) / 32), blk>>>(Wo, WoT, HH * HDD, DD);
    }

    // projections on tensor cores (mma.sync tf32x2)
    gemm_mma_tf32<<<dim3((HH * HDD) / BN, MM / BM), 256, GSMEM_BYTES>>>(
        X, WqT, Qb, MM, HH * HDD, DD);
    gemm_mma_tf32<<<dim3((KVH * HDD) / BN, MM / BM), 256, GSMEM_BYTES>>>(
        X, WkT, Kb, MM, KVH * HDD, DD);
    gemm_mma_tf32<<<dim3((KVH * HDD) / BN, MM / BM), 256, GSMEM_BYTES>>>(
        X, WvT, Vb, MM, KVH * HDD, DD);

    // RoPE
    {
        int n = LL * (HDD / 2);
        rope_table_kernel<<<(n + 255) / 256, 256>>>();
        int nq = BB * LL * HH * (HDD / 2);
        rope_apply_kernel<<<(nq + 255) / 256, 256>>>(Qb, pos, HH);
        int nk = BB * LL * KVH * (HDD / 2);
        rope_apply_kernel<<<(nk + 255) / 256, 256>>>(Kb, pos, KVH);
    }

    // attention
    flash_kernel<<<BB * HH * (LL / 64), 256, FL_SMEM_BYTES>>>(Qb, Kb, Vb, Ob);

    // output projection
    gemm_mma_tf32<<<dim3(DD / BN, MM / BM), 256, GSMEM_BYTES>>>(
        Ob, WoT, out, MM, DD, HH * HDD);
}